// round 7
// baseline (speedup 1.0000x reference)
#include <cuda_runtime.h>
#include <cstdint>
#include <math_constants.h>

#define BATCH   16384
#define S       2048
#define G       256
#define NT      256
#define EPT     (S / NT)   // 8
#define LISTCAP 32
#define RANKW   1793u      // S-G+1 ascending
#define RANKL   256u       // G ascending

// ---- order-preserving float<->uint transforms (fallback path only) ----
__device__ __forceinline__ uint32_t f2u(float f) {
    uint32_t b = __float_as_uint(f);
    return b ^ ((b & 0x80000000u) ? 0xFFFFFFFFu : 0x80000000u);
}
__device__ __forceinline__ float u2f(uint32_t u) {
    uint32_t b = (u & 0x80000000u) ? (u ^ 0x80000000u) : ~u;
    return __uint_as_float(b);
}

// monotone value->bin map; MUST be used identically everywhere
__device__ __forceinline__ int val2bin(float s) {
    int b = __float2int_rd(fmaf(s, 128.0f, 512.0f));
    return min(max(b, 0), 1023);
}

// ---- block exclusive scan (u32), 256 threads ----
__device__ __forceinline__ uint32_t block_exscan_u32(uint32_t v, uint32_t* st) {
    const uint32_t full = 0xffffffffu;
    int lane = threadIdx.x & 31, w = threadIdx.x >> 5;
    uint32_t inc = v;
#pragma unroll
    for (int o = 1; o < 32; o <<= 1) {
        uint32_t t = __shfl_up_sync(full, inc, o);
        if (lane >= o) inc += t;
    }
    if (lane == 31) st[w] = inc;
    __syncthreads();
    if (threadIdx.x < 32) {
        uint32_t t = (lane < 8) ? st[lane] : 0u;
        uint32_t it = t;
#pragma unroll
        for (int o = 1; o < 8; o <<= 1) {
            uint32_t x = __shfl_up_sync(full, it, o);
            if (lane >= o) it += x;
        }
        if (lane < 8) st[lane] = it - t;
    }
    __syncthreads();
    uint32_t r = (inc - v) + st[w];
    __syncthreads();
    return r;
}

// ---- block exclusive scan (packed u64, independent 16-bit lanes) ----
__device__ __forceinline__ unsigned long long block_exscan_u64(unsigned long long v,
                                                               unsigned long long* st) {
    const uint32_t full = 0xffffffffu;
    int lane = threadIdx.x & 31, w = threadIdx.x >> 5;
    unsigned long long inc = v;
#pragma unroll
    for (int o = 1; o < 32; o <<= 1) {
        unsigned long long t = __shfl_up_sync(full, inc, o);
        if (lane >= o) inc += t;
    }
    if (lane == 31) st[w] = inc;
    __syncthreads();
    if (threadIdx.x < 32) {
        unsigned long long t = (lane < 8) ? st[lane] : 0ull;
        unsigned long long it = t;
#pragma unroll
        for (int o = 1; o < 8; o <<= 1) {
            unsigned long long x = __shfl_up_sync(full, it, o);
            if (lane >= o) it += x;
        }
        if (lane < 8) st[lane] = it - t;
    }
    __syncthreads();
    unsigned long long r = (inc - v) + st[w];
    __syncthreads();
    return r;
}

// ---- rare fallback: exact key radix select (11/11/10 bits), one rank ----
// All 256 threads must call (contains __syncthreads). Keys derived from fr inline.
__device__ uint32_t radix_one_f(const float* fr, uint32_t rank,
                                uint32_t* hist, uint32_t* st, uint32_t* pub) {
    const int tid = threadIdx.x;
    uint32_t pfx = 0, r = rank;
#pragma unroll
    for (int rnd = 0; rnd < 3; rnd++) {
        reinterpret_cast<uint4*>(hist)[tid] = make_uint4(0, 0, 0, 0);
        reinterpret_cast<uint4*>(hist)[NT + tid] = make_uint4(0, 0, 0, 0);
        __syncthreads();
#pragma unroll
        for (int k = 0; k < EPT; k++) {
            uint32_t u = f2u(fr[k]);
            bool ok; uint32_t bin;
            if (rnd == 0)      { ok = true;                bin = u >> 21; }
            else if (rnd == 1) { ok = (u >> 21) == pfx;    bin = (u >> 10) & 0x7FFu; }
            else               { ok = (u >> 10) == pfx;    bin = u & 0x3FFu; }
            if (ok) atomicAdd(&hist[bin], 1u);
        }
        __syncthreads();
        const int nb = (rnd == 2) ? 4 : 8;
        uint32_t c[8], sum = 0;
#pragma unroll
        for (int k = 0; k < 8; k++) {
            c[k] = (k < nb) ? hist[tid * nb + k] : 0u;
            sum += c[k];
        }
        uint32_t exc = block_exscan_u32(sum, st);
        if (exc < r && r <= exc + sum) {
            uint32_t run = exc;
#pragma unroll
            for (int k = 0; k < 8; k++) {
                if (k < nb && r > run && r <= run + c[k]) {
                    pub[10] = tid * nb + k; pub[11] = r - run;
                }
                run += c[k];
            }
        }
        __syncthreads();
        uint32_t bin = pub[10]; r = pub[11];
        __syncthreads();
        pfx = (rnd == 2) ? ((pfx << 10) | bin) : ((pfx << 11) | bin);
    }
    return pfx;  // full 32-bit key
}

__global__ __launch_bounds__(NT, 5)
void portfolio_kernel(const float* __restrict__ scores,
                      const float* __restrict__ short_ratio,
                      float* __restrict__ out) {
    const int row = blockIdx.x;
    const int tid = threadIdx.x;
    const int lane = tid & 31;
    const int wid = tid >> 5;
    const uint32_t full = 0xffffffffu;

    __shared__ __align__(16) uint32_t hist[2048];
    __shared__ uint32_t st32[8];
    __shared__ unsigned long long st64[8];
    __shared__ float wmaxs[8], wmins[8];
    __shared__ uint32_t pub[12];
    __shared__ uint32_t pub2[8];
    __shared__ uint32_t cnt2[2];
    __shared__ float listW[LISTCAP], listL[LISTCAP];
    __shared__ float sredf[16];
    __shared__ unsigned long long sredu[8];

    // ---- load row, local max/min, clear histogram ----
    const float4* rowp = reinterpret_cast<const float4*>(scores + (size_t)row * S);
    float fr[8];
    float lmax = -CUDART_INF_F, lmin = CUDART_INF_F;
#pragma unroll
    for (int k = 0; k < 2; k++) {
        float4 v = rowp[tid + k * NT];
        fr[k * 4 + 0] = v.x; fr[k * 4 + 1] = v.y; fr[k * 4 + 2] = v.z; fr[k * 4 + 3] = v.w;
        lmax = fmaxf(lmax, fmaxf(fmaxf(v.x, v.y), fmaxf(v.z, v.w)));
        lmin = fminf(lmin, fminf(fminf(v.x, v.y), fminf(v.z, v.w)));
    }
    reinterpret_cast<uint4*>(hist)[tid] = make_uint4(0, 0, 0, 0);
    if (tid < 2) cnt2[tid] = 0;
#pragma unroll
    for (int o = 16; o; o >>= 1) {
        lmax = fmaxf(lmax, __shfl_xor_sync(full, lmax, o));
        lmin = fminf(lmin, __shfl_xor_sync(full, lmin, o));
    }
    if (lane == 0) { wmaxs[wid] = lmax; wmins[wid] = lmin; }
    __syncthreads();

    // ---- histogram pass (value-domain bins) ----
#pragma unroll
    for (int k = 0; k < EPT; k++) atomicAdd(&hist[val2bin(fr[k])], 1u);
    if (tid < 32) {
        float a = (lane < 8) ? wmaxs[lane] : -CUDART_INF_F;
        float b = (lane < 8) ? wmins[lane] : CUDART_INF_F;
#pragma unroll
        for (int o = 4; o; o >>= 1) {
            a = fmaxf(a, __shfl_xor_sync(full, a, o));
            b = fminf(b, __shfl_xor_sync(full, b, o));
        }
        if (lane == 0) { pub[6] = __float_as_uint(a); pub[7] = __float_as_uint(b); }
    }
    __syncthreads();
    const float maxF = __uint_as_float(pub[6]);
    const float minF = __uint_as_float(pub[7]);

    // ---- one scan locates BOTH ranks + publishes prefix counts ----
    {
        uint4 v4 = reinterpret_cast<uint4*>(hist)[tid];
        uint32_t c[4] = {v4.x, v4.y, v4.z, v4.w};
        uint32_t sum = c[0] + c[1] + c[2] + c[3];
        uint32_t exc = block_exscan_u32(sum, st32);
        if (exc < RANKW && RANKW <= exc + sum) {
            uint32_t run = exc;
#pragma unroll
            for (int k = 0; k < 4; k++) {
                if (RANKW > run && RANKW <= run + c[k]) {
                    pub[0] = tid * 4 + k; pub[1] = RANKW - run; pub[2] = run + c[k];
                }
                run += c[k];
            }
        }
        if (exc < RANKL && RANKL <= exc + sum) {
            uint32_t run = exc;
#pragma unroll
            for (int k = 0; k < 4; k++) {
                if (RANKL > run && RANKL <= run + c[k]) {
                    pub[3] = tid * 4 + k; pub[4] = RANKL - run; pub[5] = run;
                }
                run += c[k];
            }
        }
        __syncthreads();
    }
    const int binW = (int)pub[0]; const uint32_t rW = pub[1]; const uint32_t inclW = pub[2];
    const int binL = (int)pub[3]; const uint32_t rL = pub[4]; const uint32_t exclL = pub[5];

    // ---- fused: capture candidates + e[k] + coarse strict-bin sums ----
    float e[8];
    float sWc = 0.0f, sLc = 0.0f;
#pragma unroll
    for (int k = 0; k < EPT; k++) {
        float s = fr[k];
        int b = val2bin(s);
        if (b == binW) {
            uint32_t i = atomicAdd(&cnt2[0], 1u);
            if (i < LISTCAP) listW[i] = s;
        }
        if (b == binL) {
            uint32_t i = atomicAdd(&cnt2[1], 1u);
            if (i < LISTCAP) listL[i] = s;
        }
        bool useW = (b >= binW);
        float ex = __expf(useW ? (s - maxF) : (minF - s));
        e[k] = ex;
        sWc += (b > binW) ? ex : 0.0f;
        sLc += (b < binL) ? ex : 0.0f;
    }
    __syncthreads();
    const uint32_t cW = cnt2[0], cL = cnt2[1];

    // reduce coarse sums (all threads)
#pragma unroll
    for (int o = 16; o; o >>= 1) {
        sWc += __shfl_xor_sync(full, sWc, o);
        sLc += __shfl_xor_sync(full, sLc, o);
    }
    if (lane == 0) { sredf[wid] = sWc; sredf[8 + wid] = sLc; }
    __syncthreads();
    if (tid < 32) {
        float a = (lane < 8) ? sredf[lane] : 0.0f;
        float b = (lane < 8) ? sredf[8 + lane] : 0.0f;
#pragma unroll
        for (int o = 4; o; o >>= 1) {
            a += __shfl_xor_sync(full, a, o);
            b += __shfl_xor_sync(full, b, o);
        }
        if (lane == 0) { sredf[0] = a; sredf[8] = b; }
    }
    __syncthreads();
    const float sW0 = sredf[0];
    const float sL0 = sredf[8];

    float swv, slv, sW, sL;
    int nWgt, nWeq, nLlt, nLeq;
    const bool fastsel = (cW <= LISTCAP && cL <= LISTCAP);

    if (fastsel) {
        // ---- warp 0 handles W candidates, warp 1 handles L candidates ----
        if (wid < 2) {
            const uint32_t n = (wid == 0) ? cW : cL;
            float v = ((uint32_t)lane < n) ? (wid == 0 ? listW[lane] : listL[lane])
                                           : CUDART_INF_F;
#pragma unroll
            for (int k = 2; k <= 32; k <<= 1) {
#pragma unroll
                for (int j = k >> 1; j > 0; j >>= 1) {
                    float o = __shfl_xor_sync(full, v, j);
                    bool up = ((lane & k) == 0);
                    bool lower = ((lane & j) == 0);
                    float mn = fminf(v, o), mx = fmaxf(v, o);
                    v = (lower == up) ? mn : mx;
                }
            }
            uint32_t rank = (wid == 0) ? rW : rL;   // 1-based
            float sel = __shfl_sync(full, v, (int)(rank - 1));
            bool valid = ((uint32_t)lane < n);
            if (wid == 0) {
                uint32_t mgt = __ballot_sync(full, valid && v > sel);
                uint32_t meq = __ballot_sync(full, valid && v == sel);
                float cs = (valid && v > sel) ? __expf(v - maxF) : 0.0f;
#pragma unroll
                for (int o = 16; o; o >>= 1) cs += __shfl_xor_sync(full, cs, o);
                if (lane == 0) {
                    pub2[0] = __float_as_uint(sel);
                    pub2[1] = __popc(mgt);
                    pub2[2] = __popc(meq);
                    pub2[3] = __float_as_uint(cs);
                }
            } else {
                uint32_t mlt = __ballot_sync(full, valid && v < sel);
                uint32_t meq = __ballot_sync(full, valid && v == sel);
                float cs = (valid && v < sel) ? __expf(minF - v) : 0.0f;
#pragma unroll
                for (int o = 16; o; o >>= 1) cs += __shfl_xor_sync(full, cs, o);
                if (lane == 0) {
                    pub2[4] = __float_as_uint(sel);
                    pub2[5] = __popc(mlt);
                    pub2[6] = __popc(meq);
                    pub2[7] = __float_as_uint(cs);
                }
            }
        }
        __syncthreads();
        swv = __uint_as_float(pub2[0]);
        slv = __uint_as_float(pub2[4]);
        nWgt = (int)(S - inclW) + (int)pub2[1];
        nWeq = (int)pub2[2];
        sW = sW0 + __uint_as_float(pub2[3]);
        nLlt = (int)exclL + (int)pub2[5];
        nLeq = (int)pub2[6];
        sL = sL0 + __uint_as_float(pub2[7]);
    } else {
        // ---- RARE fallback: exact full-key radix select + full count pass ----
        uint32_t kW = radix_one_f(fr, RANKW, hist, st32, pub);
        uint32_t kL = radix_one_f(fr, RANKL, hist, st32, pub);
        swv = u2f(kW);
        slv = u2f(kL);
        unsigned long long packed = 0ull;
        float a2 = 0.0f, b2 = 0.0f;
#pragma unroll
        for (int k = 0; k < EPT; k++) {
            float s = fr[k];
            bool gtW = (s > swv), eqW = (s == swv), ltL = (s < slv), eqL = (s == slv);
            float ex = __expf(gtW ? (s - maxF) : (minF - s));
            a2 += gtW ? ex : 0.0f;
            b2 += ltL ? ex : 0.0f;
            packed += (unsigned long long)gtW
                    + ((unsigned long long)eqW << 16)
                    + ((unsigned long long)ltL << 32)
                    + ((unsigned long long)eqL << 48);
        }
#pragma unroll
        for (int o = 16; o; o >>= 1) {
            packed += __shfl_xor_sync(full, packed, o);
            a2 += __shfl_xor_sync(full, a2, o);
            b2 += __shfl_xor_sync(full, b2, o);
        }
        if (lane == 0) { sredu[wid] = packed; sredf[wid] = a2; sredf[8 + wid] = b2; }
        __syncthreads();
        if (tid < 32) {
            unsigned long long c = (lane < 8) ? sredu[lane] : 0ull;
            float a = (lane < 8) ? sredf[lane] : 0.0f;
            float b = (lane < 8) ? sredf[8 + lane] : 0.0f;
#pragma unroll
            for (int o = 4; o; o >>= 1) {
                c += __shfl_xor_sync(full, c, o);
                a += __shfl_xor_sync(full, a, o);
                b += __shfl_xor_sync(full, b, o);
            }
            if (lane == 0) { sredu[0] = c; sredf[0] = a; sredf[8] = b; }
        }
        __syncthreads();
        packed = sredu[0];
        sW = sredf[0];
        sL = sredf[8];
        nWgt = (int)(packed & 0xFFFFu);
        nWeq = (int)((packed >> 16) & 0xFFFFu);
        nLlt = (int)((packed >> 32) & 0xFFFFu);
        nLeq = (int)((packed >> 48) & 0xFFFFu);
    }

    const int eWc = G - nWgt;
    const int eLc = G - nLlt;
    const float expWeq = __expf(swv - maxF);
    const float expLeq = __expf(minF - slv);
    const float invW = 1.0f / (sW + (float)eWc * expWeq);
    const float invL = 1.0f / (sL + (float)eLc * expLeq);
    const float wEq = expWeq * invW;
    const float lEq = expLeq * invL;

    float4* outL = reinterpret_cast<float4*>(out + (size_t)row * S);
    float4* outSh = reinterpret_cast<float4*>(out + (size_t)BATCH * S + (size_t)row * S);
    const bool noTie = (nWeq == eWc) && (nLeq == eLc);

    if (fastsel && noTie) {
        // ---- FAST write: reuse e[k], zero expf ----
#pragma unroll
        for (int k = 0; k < 2; k++) {
            float lw[4], sw4[4];
#pragma unroll
            for (int c = 0; c < 4; c++) {
                float s = fr[k * 4 + c];
                float ex = e[k * 4 + c];
                lw[c]  = (s > swv) ? ex * invW : ((s == swv) ? wEq : 0.0f);
                sw4[c] = (s < slv) ? ex * invL : ((s == slv) ? lEq : 0.0f);
            }
            outL[tid + k * NT]  = make_float4(lw[0], lw[1], lw[2], lw[3]);
            outSh[tid + k * NT] = make_float4(sw4[0], sw4[1], sw4[2], sw4[3]);
        }
    } else if (noTie) {
        // fallback no-tie write: recompute exp (bin-based e may be invalid if binW==binL)
#pragma unroll
        for (int k = 0; k < 2; k++) {
            float lw[4], sw4[4];
#pragma unroll
            for (int c = 0; c < 4; c++) {
                float s = fr[k * 4 + c];
                bool gtW = (s > swv), ltL = (s < slv);
                float ex = __expf(gtW ? (s - maxF) : (minF - s));
                lw[c]  = gtW ? ex * invW : ((s == swv) ? wEq : 0.0f);
                sw4[c] = ltL ? ex * invL : ((s == slv) ? lEq : 0.0f);
            }
            outL[tid + k * NT]  = make_float4(lw[0], lw[1], lw[2], lw[3]);
            outSh[tid + k * NT] = make_float4(sw4[0], sw4[1], sw4[2], sw4[3]);
        }
    } else {
        // ---- RARE tie path: rank equals by global index (k, tid, c) via exscan ----
        uint32_t qW0 = 0, qW1 = 0, qL0 = 0, qL1 = 0;
#pragma unroll
        for (int c = 0; c < 4; c++) {
            qW0 += (fr[c] == swv);       qL0 += (fr[c] == slv);
            qW1 += (fr[4 + c] == swv);   qL1 += (fr[4 + c] == slv);
        }
        unsigned long long pk = (unsigned long long)qW0 | ((unsigned long long)qW1 << 16) |
                                ((unsigned long long)qL0 << 32) | ((unsigned long long)qL1 << 48);
        unsigned long long ex = block_exscan_u64(pk, st64);
        if (tid == NT - 1) sredu[7] = ex + pk;
        __syncthreads();
        unsigned long long tot = sredu[7];
        const uint32_t totW0 = (uint32_t)(tot & 0xFFFFull);
        const uint32_t totL0 = (uint32_t)((tot >> 32) & 0xFFFFull);
#pragma unroll
        for (int k = 0; k < 2; k++) {
            uint32_t beforeW = k ? totW0 + (uint32_t)((ex >> 16) & 0xFFFFull)
                                 : (uint32_t)(ex & 0xFFFFull);
            uint32_t beforeL = k ? totL0 + (uint32_t)((ex >> 48) & 0xFFFFull)
                                 : (uint32_t)((ex >> 32) & 0xFFFFull);
            float lw[4], sw4[4];
#pragma unroll
            for (int c = 0; c < 4; c++) {
                float s = fr[k * 4 + c];
                float lval = 0.0f, sval = 0.0f;
                if (s > swv) lval = __expf(s - maxF) * invW;
                else if (s == swv) { lval = (beforeW < (uint32_t)eWc) ? wEq : 0.0f; beforeW++; }
                if (s < slv) sval = __expf(minF - s) * invL;
                else if (s == slv) { sval = (beforeL < (uint32_t)eLc) ? lEq : 0.0f; beforeL++; }
                lw[c] = lval;
                sw4[c] = sval;
            }
            outL[tid + k * NT]  = make_float4(lw[0], lw[1], lw[2], lw[3]);
            outSh[tid + k * NT] = make_float4(sw4[0], sw4[1], sw4[2], sw4[3]);
        }
    }

    // ---- short_ratio passthrough (clipped) ----
    if (tid == 0) {
        float r = short_ratio[row];
        r = fminf(fmaxf(r, 0.0f), 1.0f);
        out[(size_t)2 * BATCH * S + row] = r;
    }
}

extern "C" void kernel_launch(void* const* d_in, const int* in_sizes, int n_in,
                              void* d_out, int out_size) {
    const float* scores = (const float*)d_in[0];
    const float* ratio  = (const float*)d_in[1];
    if (n_in >= 2 && in_sizes[0] == BATCH && in_sizes[1] == BATCH * S) {
        const float* t = scores; scores = ratio; ratio = t;
    }
    portfolio_kernel<<<BATCH, NT>>>(scores, ratio, (float*)d_out);
}

// round 8
// speedup vs baseline: 1.0727x; 1.0727x over previous
#include <cuda_runtime.h>
#include <cstdint>
#include <math_constants.h>

#define BATCH   16384
#define S       2048
#define G       256
#define NT      256
#define EPT     (S / NT)   // 8
#define LISTCAP 32
#define RANKW   1793u      // S-G+1 ascending
#define RANKL   256u       // G ascending

// ---- order-preserving float<->uint transforms (fallback path only) ----
__device__ __forceinline__ uint32_t f2u(float f) {
    uint32_t b = __float_as_uint(f);
    return b ^ ((b & 0x80000000u) ? 0xFFFFFFFFu : 0x80000000u);
}
__device__ __forceinline__ float u2f(uint32_t u) {
    uint32_t b = (u & 0x80000000u) ? (u ^ 0x80000000u) : ~u;
    return __uint_as_float(b);
}

// monotone value->bin map; MUST be used identically everywhere
__device__ __forceinline__ int val2bin(float s) {
    int b = __float2int_rd(fmaf(s, 128.0f, 512.0f));
    return min(max(b, 0), 1023);
}

// ---- block exclusive scan (u32), 256 threads ----
__device__ __forceinline__ uint32_t block_exscan_u32(uint32_t v, uint32_t* st) {
    const uint32_t full = 0xffffffffu;
    int lane = threadIdx.x & 31, w = threadIdx.x >> 5;
    uint32_t inc = v;
#pragma unroll
    for (int o = 1; o < 32; o <<= 1) {
        uint32_t t = __shfl_up_sync(full, inc, o);
        if (lane >= o) inc += t;
    }
    if (lane == 31) st[w] = inc;
    __syncthreads();
    if (threadIdx.x < 32) {
        uint32_t t = (lane < 8) ? st[lane] : 0u;
        uint32_t it = t;
#pragma unroll
        for (int o = 1; o < 8; o <<= 1) {
            uint32_t x = __shfl_up_sync(full, it, o);
            if (lane >= o) it += x;
        }
        if (lane < 8) st[lane] = it - t;
    }
    __syncthreads();
    uint32_t r = (inc - v) + st[w];
    __syncthreads();
    return r;
}

// ---- block exclusive scan (packed u64, independent 16-bit lanes) ----
__device__ __forceinline__ unsigned long long block_exscan_u64(unsigned long long v,
                                                               unsigned long long* st) {
    const uint32_t full = 0xffffffffu;
    int lane = threadIdx.x & 31, w = threadIdx.x >> 5;
    unsigned long long inc = v;
#pragma unroll
    for (int o = 1; o < 32; o <<= 1) {
        unsigned long long t = __shfl_up_sync(full, inc, o);
        if (lane >= o) inc += t;
    }
    if (lane == 31) st[w] = inc;
    __syncthreads();
    if (threadIdx.x < 32) {
        unsigned long long t = (lane < 8) ? st[lane] : 0ull;
        unsigned long long it = t;
#pragma unroll
        for (int o = 1; o < 8; o <<= 1) {
            unsigned long long x = __shfl_up_sync(full, it, o);
            if (lane >= o) it += x;
        }
        if (lane < 8) st[lane] = it - t;
    }
    __syncthreads();
    unsigned long long r = (inc - v) + st[w];
    __syncthreads();
    return r;
}

// ---- rare fallback: exact key radix select (11/11/10 bits), one rank ----
__device__ uint32_t radix_one_f(const float* fr, uint32_t rank,
                                uint32_t* hist, uint32_t* st, uint32_t* pub) {
    const int tid = threadIdx.x;
    uint32_t pfx = 0, r = rank;
#pragma unroll
    for (int rnd = 0; rnd < 3; rnd++) {
        reinterpret_cast<uint4*>(hist)[tid] = make_uint4(0, 0, 0, 0);
        reinterpret_cast<uint4*>(hist)[NT + tid] = make_uint4(0, 0, 0, 0);
        __syncthreads();
#pragma unroll
        for (int k = 0; k < EPT; k++) {
            uint32_t u = f2u(fr[k]);
            bool ok; uint32_t bin;
            if (rnd == 0)      { ok = true;                bin = u >> 21; }
            else if (rnd == 1) { ok = (u >> 21) == pfx;    bin = (u >> 10) & 0x7FFu; }
            else               { ok = (u >> 10) == pfx;    bin = u & 0x3FFu; }
            if (ok) atomicAdd(&hist[bin], 1u);
        }
        __syncthreads();
        const int nb = (rnd == 2) ? 4 : 8;
        uint32_t c[8], sum = 0;
#pragma unroll
        for (int k = 0; k < 8; k++) {
            c[k] = (k < nb) ? hist[tid * nb + k] : 0u;
            sum += c[k];
        }
        uint32_t exc = block_exscan_u32(sum, st);
        if (exc < r && r <= exc + sum) {
            uint32_t run = exc;
#pragma unroll
            for (int k = 0; k < 8; k++) {
                if (k < nb && r > run && r <= run + c[k]) {
                    pub[10] = tid * nb + k; pub[11] = r - run;
                }
                run += c[k];
            }
        }
        __syncthreads();
        uint32_t bin = pub[10]; r = pub[11];
        __syncthreads();
        pfx = (rnd == 2) ? ((pfx << 10) | bin) : ((pfx << 11) | bin);
    }
    return pfx;
}

__global__ __launch_bounds__(NT, 6)
void portfolio_kernel(const float* __restrict__ scores,
                      const float* __restrict__ short_ratio,
                      float* __restrict__ out) {
    const int row = blockIdx.x;
    const int tid = threadIdx.x;
    const int lane = tid & 31;
    const int wid = tid >> 5;
    const uint32_t full = 0xffffffffu;

    __shared__ __align__(16) uint32_t hist[2048];
    __shared__ uint32_t st32[8];
    __shared__ unsigned long long st64[8];
    __shared__ float wmaxs[8], wmins[8];
    __shared__ uint32_t pub[12];
    __shared__ uint32_t pub2[8];
    __shared__ uint32_t cnt2[2];
    __shared__ float listW[LISTCAP], listL[LISTCAP];
    __shared__ float sredf[16];
    __shared__ unsigned long long sredu[8];

    // ---- load row, local max/min, clear histogram ----
    const float4* rowp = reinterpret_cast<const float4*>(scores + (size_t)row * S);
    float fr[8];
    float lmax = -CUDART_INF_F, lmin = CUDART_INF_F;
#pragma unroll
    for (int k = 0; k < 2; k++) {
        float4 v = rowp[tid + k * NT];
        fr[k * 4 + 0] = v.x; fr[k * 4 + 1] = v.y; fr[k * 4 + 2] = v.z; fr[k * 4 + 3] = v.w;
        lmax = fmaxf(lmax, fmaxf(fmaxf(v.x, v.y), fmaxf(v.z, v.w)));
        lmin = fminf(lmin, fminf(fminf(v.x, v.y), fminf(v.z, v.w)));
    }
    reinterpret_cast<uint4*>(hist)[tid] = make_uint4(0, 0, 0, 0);
    if (tid < 2) cnt2[tid] = 0;
#pragma unroll
    for (int o = 16; o; o >>= 1) {
        lmax = fmaxf(lmax, __shfl_xor_sync(full, lmax, o));
        lmin = fminf(lmin, __shfl_xor_sync(full, lmin, o));
    }
    if (lane == 0) { wmaxs[wid] = lmax; wmins[wid] = lmin; }
    __syncthreads();

    // ---- histogram pass (value-domain bins); warp 0 finishes min/max meanwhile ----
#pragma unroll
    for (int k = 0; k < EPT; k++) atomicAdd(&hist[val2bin(fr[k])], 1u);
    if (tid < 32) {
        float a = (lane < 8) ? wmaxs[lane] : -CUDART_INF_F;
        float b = (lane < 8) ? wmins[lane] : CUDART_INF_F;
#pragma unroll
        for (int o = 4; o; o >>= 1) {
            a = fmaxf(a, __shfl_xor_sync(full, a, o));
            b = fminf(b, __shfl_xor_sync(full, b, o));
        }
        if (lane == 0) { pub[6] = __float_as_uint(a); pub[7] = __float_as_uint(b); }
    }
    __syncthreads();
    const float maxF = __uint_as_float(pub[6]);
    const float minF = __uint_as_float(pub[7]);

    // ---- one scan locates BOTH ranks + publishes prefix counts ----
    {
        uint4 v4 = reinterpret_cast<uint4*>(hist)[tid];
        uint32_t c[4] = {v4.x, v4.y, v4.z, v4.w};
        uint32_t sum = c[0] + c[1] + c[2] + c[3];
        uint32_t exc = block_exscan_u32(sum, st32);
        if (exc < RANKW && RANKW <= exc + sum) {
            uint32_t run = exc;
#pragma unroll
            for (int k = 0; k < 4; k++) {
                if (RANKW > run && RANKW <= run + c[k]) {
                    pub[0] = tid * 4 + k; pub[1] = RANKW - run; pub[2] = run + c[k];
                }
                run += c[k];
            }
        }
        if (exc < RANKL && RANKL <= exc + sum) {
            uint32_t run = exc;
#pragma unroll
            for (int k = 0; k < 4; k++) {
                if (RANKL > run && RANKL <= run + c[k]) {
                    pub[3] = tid * 4 + k; pub[4] = RANKL - run; pub[5] = run;
                }
                run += c[k];
            }
        }
        __syncthreads();
    }
    const int binW = (int)pub[0]; const uint32_t rW = pub[1]; const uint32_t inclW = pub[2];
    const int binL = (int)pub[3]; const uint32_t rL = pub[4]; const uint32_t exclL = pub[5];

    // ---- fused: capture candidates + coarse strict-bin exp-sums ----
    float sWc = 0.0f, sLc = 0.0f;
#pragma unroll
    for (int k = 0; k < EPT; k++) {
        float s = fr[k];
        int b = val2bin(s);
        if (b == binW) {
            uint32_t i = atomicAdd(&cnt2[0], 1u);
            if (i < LISTCAP) listW[i] = s;
        }
        if (b == binL) {
            uint32_t i = atomicAdd(&cnt2[1], 1u);
            if (i < LISTCAP) listL[i] = s;
        }
        float ex = __expf((b > binW) ? (s - maxF) : (minF - s));
        sWc += (b > binW) ? ex : 0.0f;
        sLc += (b < binL) ? ex : 0.0f;
    }
    // per-warp partials for coarse sums
#pragma unroll
    for (int o = 16; o; o >>= 1) {
        sWc += __shfl_xor_sync(full, sWc, o);
        sLc += __shfl_xor_sync(full, sLc, o);
    }
    if (lane == 0) { sredf[wid] = sWc; sredf[8 + wid] = sLc; }
    __syncthreads();
    const uint32_t cW = cnt2[0], cL = cnt2[1];
    const bool fastsel = (cW <= LISTCAP && cL <= LISTCAP);

    if (fastsel) {
        // ---- warps 0/1: sort + ballots; warp 2: finalize coarse sums (overlapped) ----
        if (wid < 2) {
            const uint32_t n = (wid == 0) ? cW : cL;
            float v = ((uint32_t)lane < n) ? (wid == 0 ? listW[lane] : listL[lane])
                                           : CUDART_INF_F;
#pragma unroll
            for (int k = 2; k <= 32; k <<= 1) {
#pragma unroll
                for (int j = k >> 1; j > 0; j >>= 1) {
                    float o = __shfl_xor_sync(full, v, j);
                    bool up = ((lane & k) == 0);
                    bool lower = ((lane & j) == 0);
                    float mn = fminf(v, o), mx = fmaxf(v, o);
                    v = (lower == up) ? mn : mx;
                }
            }
            uint32_t rank = (wid == 0) ? rW : rL;   // 1-based
            float sel = __shfl_sync(full, v, (int)(rank - 1));
            bool valid = ((uint32_t)lane < n);
            if (wid == 0) {
                uint32_t mgt = __ballot_sync(full, valid && v > sel);
                uint32_t meq = __ballot_sync(full, valid && v == sel);
                float cs = (valid && v > sel) ? __expf(v - maxF) : 0.0f;
#pragma unroll
                for (int o = 16; o; o >>= 1) cs += __shfl_xor_sync(full, cs, o);
                if (lane == 0) {
                    pub2[0] = __float_as_uint(sel);
                    pub2[1] = __popc(mgt);
                    pub2[2] = __popc(meq);
                    pub2[3] = __float_as_uint(cs);
                }
            } else {
                uint32_t mlt = __ballot_sync(full, valid && v < sel);
                uint32_t meq = __ballot_sync(full, valid && v == sel);
                float cs = (valid && v < sel) ? __expf(minF - v) : 0.0f;
#pragma unroll
                for (int o = 16; o; o >>= 1) cs += __shfl_xor_sync(full, cs, o);
                if (lane == 0) {
                    pub2[4] = __float_as_uint(sel);
                    pub2[5] = __popc(mlt);
                    pub2[6] = __popc(meq);
                    pub2[7] = __float_as_uint(cs);
                }
            }
        } else if (wid == 2) {
            float a = (lane < 8) ? sredf[lane] : 0.0f;
            float b = (lane < 8) ? sredf[8 + lane] : 0.0f;
#pragma unroll
            for (int o = 4; o; o >>= 1) {
                a += __shfl_xor_sync(full, a, o);
                b += __shfl_xor_sync(full, b, o);
            }
            if (lane == 0) { sredf[0] = a; sredf[8] = b; }
        }
        __syncthreads();
    }

    float swv, slv, sW, sL;
    int nWgt, nWeq, nLlt, nLeq;

    if (fastsel) {
        swv = __uint_as_float(pub2[0]);
        slv = __uint_as_float(pub2[4]);
        nWgt = (int)(S - inclW) + (int)pub2[1];
        nWeq = (int)pub2[2];
        sW = sredf[0] + __uint_as_float(pub2[3]);
        nLlt = (int)exclL + (int)pub2[5];
        nLeq = (int)pub2[6];
        sL = sredf[8] + __uint_as_float(pub2[7]);
    } else {
        // ---- RARE fallback: exact full-key radix select + full count pass ----
        uint32_t kW = radix_one_f(fr, RANKW, hist, st32, pub);
        uint32_t kL = radix_one_f(fr, RANKL, hist, st32, pub);
        swv = u2f(kW);
        slv = u2f(kL);
        unsigned long long packed = 0ull;
        float a2 = 0.0f, b2 = 0.0f;
#pragma unroll
        for (int k = 0; k < EPT; k++) {
            float s = fr[k];
            bool gtW = (s > swv), eqW = (s == swv), ltL = (s < slv), eqL = (s == slv);
            float ex = __expf(gtW ? (s - maxF) : (minF - s));
            a2 += gtW ? ex : 0.0f;
            b2 += ltL ? ex : 0.0f;
            packed += (unsigned long long)gtW
                    + ((unsigned long long)eqW << 16)
                    + ((unsigned long long)ltL << 32)
                    + ((unsigned long long)eqL << 48);
        }
#pragma unroll
        for (int o = 16; o; o >>= 1) {
            packed += __shfl_xor_sync(full, packed, o);
            a2 += __shfl_xor_sync(full, a2, o);
            b2 += __shfl_xor_sync(full, b2, o);
        }
        if (lane == 0) { sredu[wid] = packed; sredf[wid] = a2; sredf[8 + wid] = b2; }
        __syncthreads();
        if (tid < 32) {
            unsigned long long c = (lane < 8) ? sredu[lane] : 0ull;
            float a = (lane < 8) ? sredf[lane] : 0.0f;
            float b = (lane < 8) ? sredf[8 + lane] : 0.0f;
#pragma unroll
            for (int o = 4; o; o >>= 1) {
                c += __shfl_xor_sync(full, c, o);
                a += __shfl_xor_sync(full, a, o);
                b += __shfl_xor_sync(full, b, o);
            }
            if (lane == 0) { sredu[0] = c; sredf[0] = a; sredf[8] = b; }
        }
        __syncthreads();
        packed = sredu[0];
        sW = sredf[0];
        sL = sredf[8];
        nWgt = (int)(packed & 0xFFFFu);
        nWeq = (int)((packed >> 16) & 0xFFFFu);
        nLlt = (int)((packed >> 32) & 0xFFFFu);
        nLeq = (int)((packed >> 48) & 0xFFFFu);
    }

    const int eWc = G - nWgt;
    const int eLc = G - nLlt;
    const float expWeq = __expf(swv - maxF);
    const float expLeq = __expf(minF - slv);
    const float invW = 1.0f / (sW + (float)eWc * expWeq);
    const float invL = 1.0f / (sL + (float)eLc * expLeq);
    const float wEq = expWeq * invW;
    const float lEq = expLeq * invL;

    float4* outL = reinterpret_cast<float4*>(out + (size_t)row * S);
    float4* outSh = reinterpret_cast<float4*>(out + (size_t)BATCH * S + (size_t)row * S);
    const bool noTie = (nWeq == eWc) && (nLeq == eLc);

    if (noTie) {
        // ---- write: one expf per element, branch-free selects ----
#pragma unroll
        for (int k = 0; k < 2; k++) {
            float lw[4], sw4[4];
#pragma unroll
            for (int c = 0; c < 4; c++) {
                float s = fr[k * 4 + c];
                bool gtW = (s > swv), ltL = (s < slv);
                float ex = __expf(gtW ? (s - maxF) : (minF - s));
                lw[c]  = gtW ? ex * invW : ((s == swv) ? wEq : 0.0f);
                sw4[c] = ltL ? ex * invL : ((s == slv) ? lEq : 0.0f);
            }
            outL[tid + k * NT]  = make_float4(lw[0], lw[1], lw[2], lw[3]);
            outSh[tid + k * NT] = make_float4(sw4[0], sw4[1], sw4[2], sw4[3]);
        }
    } else {
        // ---- RARE tie path: rank equals by global index (k, tid, c) via exscan ----
        uint32_t qW0 = 0, qW1 = 0, qL0 = 0, qL1 = 0;
#pragma unroll
        for (int c = 0; c < 4; c++) {
            qW0 += (fr[c] == swv);       qL0 += (fr[c] == slv);
            qW1 += (fr[4 + c] == swv);   qL1 += (fr[4 + c] == slv);
        }
        unsigned long long pk = (unsigned long long)qW0 | ((unsigned long long)qW1 << 16) |
                                ((unsigned long long)qL0 << 32) | ((unsigned long long)qL1 << 48);
        unsigned long long ex = block_exscan_u64(pk, st64);
        if (tid == NT - 1) sredu[7] = ex + pk;
        __syncthreads();
        unsigned long long tot = sredu[7];
        const uint32_t totW0 = (uint32_t)(tot & 0xFFFFull);
        const uint32_t totL0 = (uint32_t)((tot >> 32) & 0xFFFFull);
#pragma unroll
        for (int k = 0; k < 2; k++) {
            uint32_t beforeW = k ? totW0 + (uint32_t)((ex >> 16) & 0xFFFFull)
                                 : (uint32_t)(ex & 0xFFFFull);
            uint32_t beforeL = k ? totL0 + (uint32_t)((ex >> 48) & 0xFFFFull)
                                 : (uint32_t)((ex >> 32) & 0xFFFFull);
            float lw[4], sw4[4];
#pragma unroll
            for (int c = 0; c < 4; c++) {
                float s = fr[k * 4 + c];
                float lval = 0.0f, sval = 0.0f;
                if (s > swv) lval = __expf(s - maxF) * invW;
                else if (s == swv) { lval = (beforeW < (uint32_t)eWc) ? wEq : 0.0f; beforeW++; }
                if (s < slv) sval = __expf(minF - s) * invL;
                else if (s == slv) { sval = (beforeL < (uint32_t)eLc) ? lEq : 0.0f; beforeL++; }
                lw[c] = lval;
                sw4[c] = sval;
            }
            outL[tid + k * NT]  = make_float4(lw[0], lw[1], lw[2], lw[3]);
            outSh[tid + k * NT] = make_float4(sw4[0], sw4[1], sw4[2], sw4[3]);
        }
    }

    // ---- short_ratio passthrough (clipped) ----
    if (tid == 0) {
        float r = short_ratio[row];
        r = fminf(fmaxf(r, 0.0f), 1.0f);
        out[(size_t)2 * BATCH * S + row] = r;
    }
}

extern "C" void kernel_launch(void* const* d_in, const int* in_sizes, int n_in,
                              void* d_out, int out_size) {
    const float* scores = (const float*)d_in[0];
    const float* ratio  = (const float*)d_in[1];
    if (n_in >= 2 && in_sizes[0] == BATCH && in_sizes[1] == BATCH * S) {
        const float* t = scores; scores = ratio; ratio = t;
    }
    portfolio_kernel<<<BATCH, NT>>>(scores, ratio, (float*)d_out);
}